// round 10
// baseline (speedup 1.0000x reference)
#include <cuda_runtime.h>
#include <utility>
#include <math.h>

// =====================================================================
// HiPPO-LegS reconstruction:  out = F(x),  x = 2*t/curr_t - 1,
//   F(x) = sum_{k=1..256} coef[k-1]*sqrt(2k+1)*P_k(x)  -- ONE fixed
// degree-256 polynomial evaluated at 524288 points.
//
// R10: tabulate F once per launch (piecewise Chebyshev), then evaluate
// each point in ~25 ops instead of 514:
//   k_sample: F at 256 intervals x 9 Chebyshev nodes (R9 Clenshaw, V=1)
//   k_fit:    samples -> degree-8 monomial coeffs per interval
//             (constexpr DCT + Cheb->monomial matrix, node-perturbation
//              corrected); record {c, invh, a0..a8} per interval
//   k_eval:   cheap acos -> interval index -> 3x LDS.128 -> 8-FMA Horner
// Intervals are uniform in theta=acos(x) so every interval sees <= pi/2
// of phase of the highest Legendre mode -> degree 8 suffices (~2e-5 rel).
// =====================================================================

#define NDEG 256
#define M_IV 256          // intervals
#define NN   9            // Chebyshev nodes / interval (degree 8)
#define RECW 12           // floats per interval record (48B)

static constexpr double PI_D = 3.14159265358979323846;

// ---------------- compile-time scaling machinery (Clenshaw) ----------------

__host__ __device__ constexpr double c_TH()  { return 9.5367431640625e-07; } // 2^-20
__host__ __device__ constexpr double c_RHO() { return 1048576.0; }           // 2^20

__host__ __device__ constexpr double Ak(int k) { return (2.0 * k + 1.0) / (double)(k + 1); }
__host__ __device__ constexpr double Bk(int k) { return (double)k / (double)(k + 1); }

__host__ __device__ constexpr double s_of(int k) {
    if (k >= NDEG + 1) return 1.0;
    double s = 1.0;
    for (int j = NDEG; j >= k; --j) {
        s /= Ak(j);
        if (s < c_TH()) s *= c_RHO();
    }
    return s;
}

__host__ __device__ constexpr bool boosted(int k) {
    if (k >= NDEG + 1) return false;
    double s = 1.0;
    for (int j = NDEG; j >= k; --j) {
        s /= Ak(j);
        if (s < c_TH()) {
            s *= c_RHO();
            if (j == k) return true;
        }
    }
    return false;
}

__host__ __device__ constexpr double beta_of(int k) {
    return Bk(k + 1) * s_of(k) / s_of(k + 2);
}

__host__ __device__ constexpr double csqrt(double v) {
    double g = v < 1.0 ? 1.0 : v;
    for (int i = 0; i < 100; ++i) g = 0.5 * (g + v / g);
    return g;
}

// g'_k = (s_k/s_0)*sqrt(2k+1): 1/s0 output normalization folded in.
__host__ __device__ constexpr float g_of(int k) {
    return (float)((s_of(k) / s_of(0)) * csqrt(2.0 * k + 1.0));
}

struct GTab { float v[NDEG + 1]; };
template <size_t... I>
constexpr GTab make_gtab(std::index_sequence<I...>) {
    return GTab{{ (I == 0 ? 0.0f : g_of((int)I))... }};
}
__constant__ GTab G = make_gtab(std::make_index_sequence<NDEG + 1>{});

// ---------------- constexpr cos + fit matrices ----------------

__host__ __device__ constexpr double ccos(double x) {
    while (x >  PI_D) x -= 2.0 * PI_D;
    while (x < -PI_D) x += 2.0 * PI_D;
    double x2 = x * x, term = 1.0, sum = 0.0;
    for (int m = 0; m < 18; ++m) {
        sum += term;
        term *= -x2 / ((2.0 * m + 1.0) * (2.0 * m + 2.0));
    }
    return sum;
}

struct U9 { double u[NN]; };
__host__ __device__ constexpr U9 make_U() {
    U9 r{};
    for (int i = 0; i < NN; ++i) r.u[i] = ccos(PI_D * (2 * i + 1) / (2.0 * NN));
    return r;
}
__constant__ U9 UID = make_U();

// W[q][i]: samples at ideal Chebyshev nodes -> monomial coefficients.
struct W9 { double w[NN][NN]; };
__host__ __device__ constexpr W9 make_W() {
    // Chebyshev T_p monomial coefficients, p=0..8
    constexpr int TC[NN][NN] = {
        { 1,  0,   0,   0,    0,    0,    0,   0,   0},
        { 0,  1,   0,   0,    0,    0,    0,   0,   0},
        {-1,  0,   2,   0,    0,    0,    0,   0,   0},
        { 0, -3,   0,   4,    0,    0,    0,   0,   0},
        { 1,  0,  -8,   0,    8,    0,    0,   0,   0},
        { 0,  5,   0, -20,    0,   16,    0,   0,   0},
        {-1,  0,  18,   0,  -48,    0,   32,   0,   0},
        { 0, -7,   0,  56,    0, -112,    0,  64,   0},
        { 1,  0, -32,   0,  160,    0, -256,   0, 128}};
    W9 r{};
    for (int q = 0; q < NN; ++q)
        for (int i = 0; i < NN; ++i) {
            double acc = 0.0;
            for (int p = 0; p < NN; ++p) {
                double kp = (p == 0) ? (1.0 / NN) : (2.0 / NN);
                acc += kp * ccos(p * PI_D * (2 * i + 1) / (2.0 * NN)) * TC[p][q];
            }
            r.w[q][i] = acc;
        }
    return r;
}
__constant__ W9 WC = make_W();

// ---------------- Clenshaw step chain (VV-templated, scalar c from smem) --

template <int K, int VV>
__device__ __forceinline__ void one_step(const float* __restrict__ sc,
                                         const float (&x)[VV], const float (&xr)[VV],
                                         float (&b1)[VV], float (&b2)[VV]) {
    constexpr float BETA  = (float)(-beta_of(K));
    constexpr bool  BOOST = boosted(K);
    const float c = sc[K];
#pragma unroll
    for (int v = 0; v < VV; ++v) {
        float o1 = b1[v];
        float tt = fmaf(b2[v], BETA, c);
        b1[v]    = fmaf(o1, BOOST ? xr[v] : x[v], tt);
        b2[v]    = o1;
    }
}

template <int K, int VV, size_t... J>
__device__ __forceinline__ void chunk_steps(std::index_sequence<J...>,
                                            const float* __restrict__ sc,
                                            const float (&x)[VV], const float (&xr)[VV],
                                            float (&b1)[VV], float (&b2)[VV]) {
    (one_step<K - (int)J, VV>(sc, x, xr, b1, b2), ...);
}

template <int K, int VV>
struct Step {
    static constexpr int CH = (K + 1 < 16) ? (K + 1) : 16;
    static __device__ __forceinline__ void run(const float* __restrict__ sc,
                                               const float (&x)[VV], const float (&xr)[VV],
                                               float (&b1)[VV], float (&b2)[VV]) {
        chunk_steps<K, VV>(std::make_index_sequence<CH>{}, sc, x, xr, b1, b2);
        Step<K - CH, VV>::run(sc, x, xr, b1, b2);
    }
};
template <int VV>
struct Step<-1, VV> {
    static __device__ __forceinline__ void run(const float* __restrict__,
                                               const float (&)[VV], const float (&)[VV],
                                               float (&)[VV], float (&)[VV]) {}
};

// ---------------- device scratch (static: no allocation) ----------------

__device__ float g_samples[M_IV * NN];
__device__ float g_xnode[M_IV * NN];
__device__ __align__(16) float g_rec[M_IV * RECW];

// ---------------- kernel 1: sample F at Chebyshev nodes ----------------

__global__ __launch_bounds__(128) void k_sample(const float* __restrict__ coef) {
    __shared__ float sc[NDEG + 1];
    for (int i = threadIdx.x; i <= NDEG; i += 128)
        sc[i] = (i == 0) ? 0.0f : G.v[i] * __ldg(coef + i - 1);
    __syncthreads();

    int gid = blockIdx.x * 128 + threadIdx.x;
    if (gid >= M_IV * NN) return;
    int j = gid / NN, i = gid % NN;

    double D  = PI_D / M_IV;
    double xh = cos(j * D), xl = cos((j + 1) * D);
    double c  = 0.5 * (xh + xl), h = 0.5 * (xh - xl);
    float  xf = (float)(c + h * UID.u[i]);

    constexpr float RHOF = (float)c_RHO();
    float x[1]  = {xf};
    float xr[1] = {xf * RHOF};
    float b1[1] = {0.0f}, b2[1] = {0.0f};
    Step<NDEG, 1>::run(sc, x, xr, b1, b2);

    g_samples[gid] = b1[0];
    g_xnode[gid]   = xf;
}

// ---------------- kernel 2: fit per-interval monomial coefficients -------

__global__ __launch_bounds__(128) void k_fit() {
    int j = blockIdx.x * 128 + threadIdx.x;
    if (j >= M_IV) return;

    double D  = PI_D / M_IV;
    double xh = cos(j * D), xl = cos((j + 1) * D);
    double c  = 0.5 * (xh + xl), h = 0.5 * (xh - xl);
    float  cf = (float)c;
    float  invhf = (float)(1.0 / h);

    double s[NN], up[NN];
    for (int i = 0; i < NN; ++i) {
        s[i]  = (double)g_samples[j * NN + i];
        // exact eval-time node coordinate (matches k_eval arithmetic)
        up[i] = ((double)g_xnode[j * NN + i] - (double)cf) * (double)invhf;
    }

    double mon[NN];
    for (int q = 0; q < NN; ++q) {
        double a = 0.0;
        for (int i = 0; i < NN; ++i) a += WC.w[q][i] * s[i];
        mon[q] = a;
    }
    // first-order node-perturbation correction: s_i at ideal node u_i is
    // approx s_i - (u'_i - u_i) * p'(u_i); refit.
    for (int i = 0; i < NN; ++i) {
        double d = 0.0;
        for (int q = NN - 1; q >= 1; --q) d = d * UID.u[i] + q * mon[q];
        s[i] -= (up[i] - UID.u[i]) * d;
    }
    for (int q = 0; q < NN; ++q) {
        double a = 0.0;
        for (int i = 0; i < NN; ++i) a += WC.w[q][i] * s[i];
        mon[q] = a;
    }

    float* r = g_rec + j * RECW;
    r[0] = cf; r[1] = invhf;
    for (int q = 0; q < NN; ++q) r[2 + q] = (float)mon[q];
    r[11] = 0.0f;
}

// ---------------- kernel 3: evaluate ----------------

#define EV_TPB 128
#define EV_V   4

__global__ __launch_bounds__(EV_TPB) void k_eval(
    const float* __restrict__ t, const int* __restrict__ ctp,
    float* __restrict__ out, int n)
{
    __shared__ __align__(16) float sm[M_IV * RECW];   // 12 KB table
    {
        const float4* src = reinterpret_cast<const float4*>(g_rec);
        float4*       dst = reinterpret_cast<float4*>(sm);
        for (int i = threadIdx.x; i < M_IV * RECW / 4; i += EV_TPB)
            dst[i] = src[i];
    }
    __syncthreads();

    float ct = 1.0f;
    if (ctp) {
        int iv   = *ctp;
        float fv = __int_as_float(iv);
        ct = (iv > 0 && iv < (1 << 20)) ? (float)iv : fv;
    }
    const float sc2 = 2.0f / ct;

    const long long base = ((long long)blockIdx.x * EV_TPB + threadIdx.x) * EV_V;
    if (base >= n) return;

    const float PI_F    = (float)PI_D;
    const float THSCALE = (float)(M_IV / PI_D);

    float tv[EV_V];
    bool full = (base + EV_V <= n);
    if (full) {
        float4 ta = *reinterpret_cast<const float4*>(t + base);
        tv[0] = ta.x; tv[1] = ta.y; tv[2] = ta.z; tv[3] = ta.w;
    } else {
#pragma unroll
        for (int v = 0; v < EV_V; ++v) {
            long long idx = base + v;
            tv[v] = (idx < n) ? t[idx] : 0.0f;
        }
    }

    float res[EV_V];
#pragma unroll
    for (int v = 0; v < EV_V; ++v) {
        float x  = fmaf(tv[v], sc2, -1.0f);
        float ax = fminf(fabsf(x), 1.0f);
        // Hastings acos approx, |err| <= 6.7e-5 rad (indexing only)
        float r  = fmaf(fmaf(fmaf(-0.0187293f, ax, 0.0742610f), ax,
                             -0.2121144f), ax, 1.5707288f);
        float sq = sqrtf(1.0f - ax);
        float vv = r * sq;                 // acos(|x|)
        float th = (x < 0.0f) ? (PI_F - vv) : vv;
        int j = (int)(th * THSCALE);
        j = min(j, M_IV - 1);

        const float4* rp = reinterpret_cast<const float4*>(sm) + j * 3;
        float4 q0 = rp[0];                 // {c, invh, a0, a1}
        float4 q1 = rp[1];                 // {a2, a3, a4, a5}
        float4 q2 = rp[2];                 // {a6, a7, a8, pad}

        float u = (x - q0.x) * q0.y;       // exact x-c (Sterbenz), scaled
        float a = q2.z;
        a = fmaf(a, u, q2.y);
        a = fmaf(a, u, q2.x);
        a = fmaf(a, u, q1.w);
        a = fmaf(a, u, q1.z);
        a = fmaf(a, u, q1.y);
        a = fmaf(a, u, q1.x);
        a = fmaf(a, u, q0.w);
        a = fmaf(a, u, q0.z);
        res[v] = a;
    }

    if (full) {
        *reinterpret_cast<float4*>(out + base) =
            make_float4(res[0], res[1], res[2], res[3]);
    } else {
#pragma unroll
        for (int v = 0; v < EV_V; ++v) {
            long long idx = base + v;
            if (idx < n) out[idx] = res[v];
        }
    }
}

// ---------------- launch ----------------

extern "C" void kernel_launch(void* const* d_in, const int* in_sizes, int n_in,
                              void* d_out, int out_size)
{
    // Identify inputs by size: big -> t, 1 -> curr_t, remaining -> coef
    int ti = -1, ci = -1, si = -1;
    for (int i = 0; i < n_in; ++i) {
        if (in_sizes[i] == out_size && ti < 0)      ti = i;
        else if (in_sizes[i] == 1 && si < 0)        si = i;
        else if (ci < 0)                            ci = i;
    }
    if (ti < 0) ti = 0;
    if (ci < 0) ci = (n_in > 1 ? 1 : 0);

    const float* t    = (const float*)d_in[ti];
    const float* coef = (const float*)d_in[ci];
    const int*   ct   = (si >= 0) ? (const int*)d_in[si] : nullptr;

    int n = out_size;

    int sb = (M_IV * NN + 127) / 128;           // 18 blocks
    k_sample<<<sb, 128>>>(coef);
    k_fit<<<(M_IV + 127) / 128, 128>>>();       // 2 blocks

    int epb    = EV_TPB * EV_V;
    int blocks = (n + epb - 1) / epb;           // 1024 blocks
    k_eval<<<blocks, EV_TPB>>>(t, ct, (float*)d_out, n);
}

// round 11
// speedup vs baseline: 1.2684x; 1.2684x over previous
#include <cuda_runtime.h>
#include <utility>
#include <math.h>

// =====================================================================
// HiPPO-LegS reconstruction:  out = F(x),  x = 2*t/curr_t - 1,
//   F(x) = sum_{k=1..256} coef[k-1]*sqrt(2k+1)*P_k(x)
// = ONE fixed degree-256 polynomial at 524288 points.
//
// R11 (pipeline fix of R10, eval math validated at rel_err 1.4e-5):
//  k_build (64 blocks): per interval, sample F at 9 Chebyshev nodes via
//    the FORWARD Legendre recurrence (1-FFMA critical chain, looped,
//    ~200B body -> no cold-I$ penalty that cost R10's k_sample 8.2us),
//    then fit degree-8 monomial coeffs in-block (9x9 constexpr DCT,
//    node-perturbation corrected) -> record {c, invh, a0..a8}.
//  k_eval (1024 blocks): cheap acos -> theta-uniform interval index ->
//    3x LDS.128 -> 8-FMA Horner.
// =====================================================================

#define NDEG 256
#define M_IV 256          // intervals (theta-uniform)
#define NN   9            // Chebyshev nodes / interval (degree 8)
#define RECW 12           // floats per interval record (48B)
#define IVB  4            // intervals per k_build block
#define TPB_B 128

static constexpr double PI_D = 3.14159265358979323846;

// ---------------- constexpr helpers ----------------

__host__ __device__ constexpr double csqrt(double v) {
    double g = v < 1.0 ? 1.0 : v;
    for (int i = 0; i < 100; ++i) g = 0.5 * (g + v / g);
    return g;
}

__host__ __device__ constexpr double ccos(double x) {
    while (x >  PI_D) x -= 2.0 * PI_D;
    while (x < -PI_D) x += 2.0 * PI_D;
    double x2 = x * x, term = 1.0, sum = 0.0;
    for (int m = 0; m < 18; ++m) {
        sum += term;
        term *= -x2 / ((2.0 * m + 1.0) * (2.0 * m + 2.0));
    }
    return sum;
}

// sqrt(2k+1) table
struct SQT { float v[NDEG + 2]; };
template <size_t... I>
constexpr SQT make_sq(std::index_sequence<I...>) {
    return SQT{{ ((float)csqrt(2.0 * (double)I + 1.0))... }};
}
__constant__ SQT SQ = make_sq(std::make_index_sequence<NDEG + 2>{});

// ideal Chebyshev nodes u_i = cos(pi(2i+1)/18)
struct U9 { double u[NN]; };
__host__ __device__ constexpr U9 make_U() {
    U9 r{};
    for (int i = 0; i < NN; ++i) r.u[i] = ccos(PI_D * (2 * i + 1) / (2.0 * NN));
    return r;
}
__constant__ U9 UID = make_U();

// W[q][i]: samples at ideal nodes -> monomial coefficients (degree 8)
struct W9 { double w[NN][NN]; };
__host__ __device__ constexpr W9 make_W() {
    constexpr int TC[NN][NN] = {
        { 1,  0,   0,   0,    0,    0,    0,   0,   0},
        { 0,  1,   0,   0,    0,    0,    0,   0,   0},
        {-1,  0,   2,   0,    0,    0,    0,   0,   0},
        { 0, -3,   0,   4,    0,    0,    0,   0,   0},
        { 1,  0,  -8,   0,    8,    0,    0,   0,   0},
        { 0,  5,   0, -20,    0,   16,    0,   0,   0},
        {-1,  0,  18,   0,  -48,    0,   32,   0,   0},
        { 0, -7,   0,  56,    0, -112,    0,  64,   0},
        { 1,  0, -32,   0,  160,    0, -256,   0, 128}};
    W9 r{};
    for (int q = 0; q < NN; ++q)
        for (int i = 0; i < NN; ++i) {
            double acc = 0.0;
            for (int p = 0; p < NN; ++p) {
                double kp = (p == 0) ? (1.0 / NN) : (2.0 / NN);
                acc += kp * ccos(p * PI_D * (2 * i + 1) / (2.0 * NN)) * TC[p][q];
            }
            r.w[q][i] = acc;
        }
    return r;
}
__constant__ W9 WC = make_W();

// ---------------- device scratch (static: no allocation) ----------------

__device__ __align__(16) float g_rec[M_IV * RECW];

// ---------------- kernel 1: sample + fit (fused) ----------------

__global__ __launch_bounds__(TPB_B) void k_build(const float* __restrict__ coef) {
    // Forward-recurrence step constants: tab[k] = {a_k, -b_k, w_{k+1}, 0}
    //   a_k = (2k+1)/(k+1), b_k = k/(k+1), w_m = sqrt(2m+1)*coef[m-1]
    __shared__ float4 tab[NDEG];              // k = 1..255 used
    __shared__ float  s_s[IVB][NN];           // samples
    __shared__ float  s_x[IVB][NN];           // node x (float, as evaluated)
    __shared__ double s_mon[IVB][NN];         // pass-1 monomial coeffs

    for (int k = threadIdx.x; k < NDEG; k += TPB_B) {
        if (k >= 1) {
            float a = (2.0f * k + 1.0f) / (float)(k + 1);
            float b = -(float)k / (float)(k + 1);
            float w = SQ.v[k + 1] * __ldg(coef + k);
            tab[k] = make_float4(a, b, w, 0.0f);
        } else {
            tab[0] = make_float4(0.f, 0.f, 0.f, 0.f);
        }
    }
    __syncthreads();

    const int ivl  = threadIdx.x / NN;        // local interval 0..IVB-1
    const int node = threadIdx.x % NN;
    const int j    = blockIdx.x * IVB + ivl;  // global interval

    const double D = PI_D / M_IV;

    // ---- phase 1: sample F at this interval's 9 Chebyshev nodes ----
    if (threadIdx.x < IVB * NN) {
        double xh = cos(j * D), xl = cos((j + 1) * D);
        double c  = 0.5 * (xh + xl), h = 0.5 * (xh - xl);
        float  x  = (float)(c + h * UID.u[node]);

        float pm1 = 1.0f, p = x;
        float acc = (SQ.v[1] * __ldg(coef)) * x;   // w_1 * P_1
#pragma unroll 4
        for (int k = 1; k < NDEG; ++k) {
            float4 q  = tab[k];
            float  ax = q.x * x;                   // off critical chain
            float  tt = q.y * pm1;                 // off critical chain
            float  pn = fmaf(ax, p, tt);           // chain: 1 FFMA/step
            acc = fmaf(q.z, pn, acc);              // separate acc chain
            pm1 = p; p = pn;
        }
        s_s[ivl][node] = acc;
        s_x[ivl][node] = x;
    }
    __syncthreads();

    // ---- phase 2: first-pass fit (thread = (iv, q)) ----
    if (threadIdx.x < IVB * NN) {
        int q = node;
        double a = 0.0;
        for (int i = 0; i < NN; ++i) a += WC.w[q][i] * (double)s_s[ivl][i];
        s_mon[ivl][q] = a;
    }
    __syncthreads();

    // ---- phase 3: node-perturbation correction (thread = (iv, i)) ----
    float corr_s = 0.0f;
    if (threadIdx.x < IVB * NN) {
        int i = node;
        double xh = cos(j * D), xl = cos((j + 1) * D);
        double c  = 0.5 * (xh + xl), h = 0.5 * (xh - xl);
        float  cf = (float)c;
        float  invhf = (float)(1.0 / h);
        double up = ((double)s_x[ivl][i] - (double)cf) * (double)invhf;
        double d  = 0.0;
        for (int q = NN - 1; q >= 1; --q) d = d * UID.u[i] + q * s_mon[ivl][q];
        corr_s = (float)((double)s_s[ivl][i] - (up - UID.u[i]) * d);
    }
    __syncthreads();
    if (threadIdx.x < IVB * NN) s_s[ivl][node] = corr_s;
    __syncthreads();

    // ---- phase 4: final fit + write record (thread = (iv, q)) ----
    if (threadIdx.x < IVB * NN) {
        int q = node;
        double a = 0.0;
        for (int i = 0; i < NN; ++i) a += WC.w[q][i] * (double)s_s[ivl][i];
        float* r = g_rec + j * RECW;
        r[2 + q] = (float)a;
        if (q == 0) {
            double xh = cos(j * D), xl = cos((j + 1) * D);
            double c  = 0.5 * (xh + xl), h = 0.5 * (xh - xl);
            r[0]  = (float)c;
            r[1]  = (float)(1.0 / h);
            r[11] = 0.0f;
        }
    }
}

// ---------------- kernel 2: evaluate ----------------

#define EV_TPB 128
#define EV_V   4

__global__ __launch_bounds__(EV_TPB) void k_eval(
    const float* __restrict__ t, const int* __restrict__ ctp,
    float* __restrict__ out, int n)
{
    __shared__ __align__(16) float sm[M_IV * RECW];   // 12 KB table
    {
        const float4* src = reinterpret_cast<const float4*>(g_rec);
        float4*       dst = reinterpret_cast<float4*>(sm);
        for (int i = threadIdx.x; i < M_IV * RECW / 4; i += EV_TPB)
            dst[i] = src[i];
    }
    __syncthreads();

    float ct = 1.0f;
    if (ctp) {
        int iv   = *ctp;
        float fv = __int_as_float(iv);
        ct = (iv > 0 && iv < (1 << 20)) ? (float)iv : fv;
    }
    const float sc2 = 2.0f / ct;

    const long long base = ((long long)blockIdx.x * EV_TPB + threadIdx.x) * EV_V;
    if (base >= n) return;

    const float PI_F    = (float)PI_D;
    const float THSCALE = (float)(M_IV / PI_D);

    float tv[EV_V];
    bool full = (base + EV_V <= n);
    if (full) {
        float4 ta = *reinterpret_cast<const float4*>(t + base);
        tv[0] = ta.x; tv[1] = ta.y; tv[2] = ta.z; tv[3] = ta.w;
    } else {
#pragma unroll
        for (int v = 0; v < EV_V; ++v) {
            long long idx = base + v;
            tv[v] = (idx < n) ? t[idx] : 0.0f;
        }
    }

    float res[EV_V];
#pragma unroll
    for (int v = 0; v < EV_V; ++v) {
        float x  = fmaf(tv[v], sc2, -1.0f);
        float ax = fminf(fabsf(x), 1.0f);
        // Hastings acos approx (indexing only; ~6.7e-5 rad)
        float r  = fmaf(fmaf(fmaf(-0.0187293f, ax, 0.0742610f), ax,
                             -0.2121144f), ax, 1.5707288f);
        float sq = sqrtf(1.0f - ax);
        float vv = r * sq;
        float th = (x < 0.0f) ? (PI_F - vv) : vv;
        int j = (int)(th * THSCALE);
        j = min(j, M_IV - 1);

        const float4* rp = reinterpret_cast<const float4*>(sm) + j * 3;
        float4 q0 = rp[0];                 // {c, invh, a0, a1}
        float4 q1 = rp[1];                 // {a2, a3, a4, a5}
        float4 q2 = rp[2];                 // {a6, a7, a8, pad}

        float u = (x - q0.x) * q0.y;
        float a = q2.z;
        a = fmaf(a, u, q2.y);
        a = fmaf(a, u, q2.x);
        a = fmaf(a, u, q1.w);
        a = fmaf(a, u, q1.z);
        a = fmaf(a, u, q1.y);
        a = fmaf(a, u, q1.x);
        a = fmaf(a, u, q0.w);
        a = fmaf(a, u, q0.z);
        res[v] = a;
    }

    if (full) {
        *reinterpret_cast<float4*>(out + base) =
            make_float4(res[0], res[1], res[2], res[3]);
    } else {
#pragma unroll
        for (int v = 0; v < EV_V; ++v) {
            long long idx = base + v;
            if (idx < n) out[idx] = res[v];
        }
    }
}

// ---------------- launch ----------------

extern "C" void kernel_launch(void* const* d_in, const int* in_sizes, int n_in,
                              void* d_out, int out_size)
{
    // Identify inputs by size: big -> t, 1 -> curr_t, remaining -> coef
    int ti = -1, ci = -1, si = -1;
    for (int i = 0; i < n_in; ++i) {
        if (in_sizes[i] == out_size && ti < 0)      ti = i;
        else if (in_sizes[i] == 1 && si < 0)        si = i;
        else if (ci < 0)                            ci = i;
    }
    if (ti < 0) ti = 0;
    if (ci < 0) ci = (n_in > 1 ? 1 : 0);

    const float* t    = (const float*)d_in[ti];
    const float* coef = (const float*)d_in[ci];
    const int*   ct   = (si >= 0) ? (const int*)d_in[si] : nullptr;

    int n = out_size;

    k_build<<<M_IV / IVB, TPB_B>>>(coef);     // 64 blocks

    int epb    = EV_TPB * EV_V;
    int blocks = (n + epb - 1) / epb;         // 1024 blocks
    k_eval<<<blocks, EV_TPB>>>(t, ct, (float*)d_out, n);
}

// round 13
// speedup vs baseline: 1.5200x; 1.1983x over previous
#include <cuda_runtime.h>
#include <utility>
#include <math.h>

// =====================================================================
// HiPPO-LegS reconstruction:  out = F(x),  x = 2*t/curr_t - 1.
// F(cos(theta)) is EXACTLY a degree-256 trig polynomial in theta, so a
// piecewise-cubic fit on M=1024 UNIFORM theta-intervals is uniformly
// accurate (~7e-6 rel truncation) and needs no per-record {c, invh}:
//   k_build (32 blocks): forward Legendre recurrence (bounded, no
//     rescaling; float4 smem tab, 5 instr/step) at 4 Chebyshev nodes
//     per interval; constexpr 4x4 Cheb->monomial fit -> float4 record.
//   k_eval (1024 blocks): theta=acosf(x); j=theta*M/pi; u=2*frac-1;
//     ONE __ldg float4 gather (16KB table, L1-resident, no smem stage,
//     no syncthreads); 3-FMA Horner.
// vs R11: gather bytes 48->16, eval instrs ~2x fewer, k_build loses all
// libdevice double transcendentals except one cos().
// =====================================================================

#define NDEG  256
#define M_IV  1024
#define NNODE 4
#define IVB   32
#define TPB_B 128
#define EV_TPB 128
#define EV_V   4

static constexpr double PI_D = 3.14159265358979323846;

// ---------------- constexpr helpers ----------------

__host__ __device__ constexpr double csqrt(double v) {
    double g = v < 1.0 ? 1.0 : v;
    for (int i = 0; i < 100; ++i) g = 0.5 * (g + v / g);
    return g;
}

__host__ __device__ constexpr double ccos(double x) {
    while (x >  PI_D) x -= 2.0 * PI_D;
    while (x < -PI_D) x += 2.0 * PI_D;
    double x2 = x * x, term = 1.0, sum = 0.0;
    for (int m = 0; m < 18; ++m) {
        sum += term;
        term *= -x2 / ((2.0 * m + 1.0) * (2.0 * m + 2.0));
    }
    return sum;
}

// sqrt(2m+1) table for w_m = sqrt(2m+1)*coef[m-1]
struct SQT { float v[NDEG + 2]; };
template <size_t... I>
constexpr SQT make_sq(std::index_sequence<I...>) {
    return SQT{{ ((float)csqrt(2.0 * (double)I + 1.0))... }};
}
__constant__ SQT SQ = make_sq(std::make_index_sequence<NDEG + 2>{});

// Chebyshev nodes u_i = cos(pi(2i+1)/8), i=0..3
struct U4T { double u[NNODE]; };
__host__ __device__ constexpr U4T make_U4() {
    U4T r{};
    for (int i = 0; i < NNODE; ++i) r.u[i] = ccos(PI_D * (2 * i + 1) / 8.0);
    return r;
}
__constant__ U4T U4 = make_U4();

// W4[q][i]: samples at 4 Chebyshev nodes -> monomial coeffs (degree 3)
struct W4T { double w[NNODE][NNODE]; };
__host__ __device__ constexpr W4T make_W4() {
    W4T r{};
    for (int i = 0; i < NNODE; ++i) {
        double c[4] = {0.0, 0.0, 0.0, 0.0};
        for (int p = 0; p < 4; ++p) {
            double kp = (p == 0) ? 0.25 : 0.5;
            c[p] = kp * ccos(p * PI_D * (2 * i + 1) / 8.0);
        }
        // T0=1, T1=u, T2=2u^2-1, T3=4u^3-3u
        r.w[0][i] = c[0] - c[2];
        r.w[1][i] = c[1] - 3.0 * c[3];
        r.w[2][i] = 2.0 * c[2];
        r.w[3][i] = 4.0 * c[3];
    }
    return r;
}
__constant__ W4T W4 = make_W4();

// ---------------- device scratch (static: no allocation) ----------------

__device__ __align__(16) float g_rec[M_IV * 4];   // 16 KB: {m0,m1,m2,m3}/interval

// ---------------- kernel 1: sample + fit ----------------

__global__ __launch_bounds__(TPB_B) void k_build(const float* __restrict__ coef) {
    // tab[k] = {a_k, -b_k, w_{k+1}, 0}; tab[0].z = w_1
    __shared__ float4 tab[NDEG];
    __shared__ float  s_smp[IVB][NNODE];

    for (int k = threadIdx.x; k < NDEG; k += TPB_B) {
        float a = 0.0f, b = 0.0f;
        if (k >= 1) {
            a = (2.0f * k + 1.0f) / (float)(k + 1);
            b = -(float)k / (float)(k + 1);
        }
        float w = SQ.v[k + 1] * __ldg(coef + k);   // w_{k+1}
        tab[k] = make_float4(a, b, w, 0.0f);
    }
    __syncthreads();

    const int iv   = threadIdx.x >> 2;            // 0..31
    const int node = threadIdx.x & 3;             // 0..3
    const int j    = blockIdx.x * IVB + iv;       // global interval

    const double Delta = PI_D / M_IV;
    double th = (j + 0.5) * Delta + 0.5 * Delta * U4.u[node];
    float  x  = (float)cos(th);                   // arg < pi: fast path

    // forward Legendre recurrence (P_k bounded on [-1,1]: no rescaling)
    float pm1 = 1.0f, p = x;
    float acc = tab[0].z * x;                     // w_1 * P_1
#pragma unroll 8
    for (int k = 1; k < NDEG; ++k) {
        float4 q  = tab[k];
        float  pn = fmaf(q.x * x, p, q.y * pm1);  // chain: 1 FFMA/step
        acc = fmaf(q.z, pn, acc);
        pm1 = p; p = pn;
    }
    s_smp[iv][node] = acc;
    __syncthreads();

    // fit: thread (iv, q=node) computes monomial coeff q of its interval
    double a = 0.0;
#pragma unroll
    for (int i = 0; i < NNODE; ++i)
        a += W4.w[node][i] * (double)s_smp[iv][i];
    g_rec[j * 4 + node] = (float)a;
}

// ---------------- kernel 2: evaluate ----------------

__global__ __launch_bounds__(EV_TPB) void k_eval(
    const float* __restrict__ t, const int* __restrict__ ctp,
    float* __restrict__ out, int n)
{
    float ct = 1.0f;
    if (ctp) {
        int iv   = *ctp;
        float fv = __int_as_float(iv);
        ct = (iv > 0 && iv < (1 << 20)) ? (float)iv : fv;
    }
    const float sc2 = 2.0f / ct;

    const long long base = ((long long)blockIdx.x * EV_TPB + threadIdx.x) * EV_V;
    if (base >= n) return;

    const float THSCALE = (float)(M_IV / PI_D);
    const float4* __restrict__ rec = reinterpret_cast<const float4*>(g_rec);

    float tv[EV_V];
    bool full = (base + EV_V <= n);
    if (full) {
        float4 ta = *reinterpret_cast<const float4*>(t + base);
        tv[0] = ta.x; tv[1] = ta.y; tv[2] = ta.z; tv[3] = ta.w;
    } else {
#pragma unroll
        for (int v = 0; v < EV_V; ++v) {
            long long idx = base + v;
            tv[v] = (idx < n) ? t[idx] : 0.0f;
        }
    }

    float res[EV_V];
#pragma unroll
    for (int v = 0; v < EV_V; ++v) {
        float x  = fmaf(tv[v], sc2, -1.0f);
        x = fminf(fmaxf(x, -1.0f), 1.0f);
        float th = acosf(x);                  // ~2 ulp: theta error ~5e-7 rad
        float f  = th * THSCALE;              // in [0, 1024]
        int   j  = min((int)f, M_IV - 1);
        float u  = fmaf(2.0f, f - (float)j, -1.0f);   // in [-1, 1]

        float4 m = __ldg(rec + j);            // L1-resident 16 KB table
        float  r = fmaf(fmaf(fmaf(m.w, u, m.z), u, m.y), u, m.x);
        res[v] = r;
    }

    if (full) {
        *reinterpret_cast<float4*>(out + base) =
            make_float4(res[0], res[1], res[2], res[3]);
    } else {
#pragma unroll
        for (int v = 0; v < EV_V; ++v) {
            long long idx = base + v;
            if (idx < n) out[idx] = res[v];
        }
    }
}

// ---------------- launch ----------------

extern "C" void kernel_launch(void* const* d_in, const int* in_sizes, int n_in,
                              void* d_out, int out_size)
{
    // Identify inputs by size: big -> t, 1 -> curr_t, remaining -> coef
    int ti = -1, ci = -1, si = -1;
    for (int i = 0; i < n_in; ++i) {
        if (in_sizes[i] == out_size && ti < 0)      ti = i;
        else if (in_sizes[i] == 1 && si < 0)        si = i;
        else if (ci < 0)                            ci = i;
    }
    if (ti < 0) ti = 0;
    if (ci < 0) ci = (n_in > 1 ? 1 : 0);

    const float* t    = (const float*)d_in[ti];
    const float* coef = (const float*)d_in[ci];
    const int*   ct   = (si >= 0) ? (const int*)d_in[si] : nullptr;

    int n = out_size;

    k_build<<<M_IV / IVB, TPB_B>>>(coef);     // 32 blocks

    int epb    = EV_TPB * EV_V;
    int blocks = (n + epb - 1) / epb;         // 1024 blocks
    k_eval<<<blocks, EV_TPB>>>(t, ct, (float*)d_out, n);
}

// round 14
// speedup vs baseline: 1.7743x; 1.1673x over previous
#include <cuda_runtime.h>
#include <utility>
#include <math.h>

// =====================================================================
// HiPPO-LegS reconstruction:  out = F(x),  x = 2*t/curr_t - 1.
// F(cos(theta)) is a degree-256 trig polynomial in theta -> piecewise
// cubic on M=1024 uniform theta-intervals (validated R13, 5.2e-5).
//
// R14: SINGLE kernel (two-kernel split cost ~10us in R13):
//  - blocks 0..31 build the 16KB table (forward Legendre recurrence at
//    4 Chebyshev nodes/interval + constexpr 4x4 fit), threadfence,
//    atomicAdd done-counter
//  - ALL 1024 blocks (co-resident: 7 blocks/SM, single wave -> spin is
//    deadlock-free) wait on the counter, stage table to smem, evaluate:
//    acosf -> uniform index -> ONE LDS.128 gather -> 3-FMA Horner
//  - last-block reset of counters => identical state每 every replay
// =====================================================================

#define NDEG  256
#define M_IV  1024
#define NNODE 4
#define IVB   32          // intervals per builder chunk (one block-chunk)
#define NCHUNK (M_IV / IVB)   // 32 builder chunks
#define TPB   128
#define EV_V  4

static constexpr double PI_D = 3.14159265358979323846;

// ---------------- constexpr helpers ----------------

__host__ __device__ constexpr double csqrt(double v) {
    double g = v < 1.0 ? 1.0 : v;
    for (int i = 0; i < 100; ++i) g = 0.5 * (g + v / g);
    return g;
}

__host__ __device__ constexpr double ccos(double x) {
    while (x >  PI_D) x -= 2.0 * PI_D;
    while (x < -PI_D) x += 2.0 * PI_D;
    double x2 = x * x, term = 1.0, sum = 0.0;
    for (int m = 0; m < 18; ++m) {
        sum += term;
        term *= -x2 / ((2.0 * m + 1.0) * (2.0 * m + 2.0));
    }
    return sum;
}

struct SQT { float v[NDEG + 2]; };
template <size_t... I>
constexpr SQT make_sq(std::index_sequence<I...>) {
    return SQT{{ ((float)csqrt(2.0 * (double)I + 1.0))... }};
}
__constant__ SQT SQ = make_sq(std::make_index_sequence<NDEG + 2>{});

struct U4T { double u[NNODE]; };
__host__ __device__ constexpr U4T make_U4() {
    U4T r{};
    for (int i = 0; i < NNODE; ++i) r.u[i] = ccos(PI_D * (2 * i + 1) / 8.0);
    return r;
}
__constant__ U4T U4 = make_U4();

struct W4T { double w[NNODE][NNODE]; };
__host__ __device__ constexpr W4T make_W4() {
    W4T r{};
    for (int i = 0; i < NNODE; ++i) {
        double c[4] = {0.0, 0.0, 0.0, 0.0};
        for (int p = 0; p < 4; ++p) {
            double kp = (p == 0) ? 0.25 : 0.5;
            c[p] = kp * ccos(p * PI_D * (2 * i + 1) / 8.0);
        }
        r.w[0][i] = c[0] - c[2];
        r.w[1][i] = c[1] - 3.0 * c[3];
        r.w[2][i] = 2.0 * c[2];
        r.w[3][i] = 4.0 * c[3];
    }
    return r;
}
__constant__ W4T W4 = make_W4();

// ---------------- device scratch (static: no allocation) ----------------

__device__ __align__(16) float g_rec[M_IV * 4];   // 16 KB table
__device__ volatile int g_done;                   // builder chunks finished
__device__ int g_exit;                            // blocks finished (reset)

// ---------------- fused kernel ----------------

__global__ __launch_bounds__(TPB) void hippo_fused(
    const float* __restrict__ t, const float* __restrict__ coef,
    const int* __restrict__ ctp, float* __restrict__ out, int n)
{
    __shared__ float4 tab[NDEG];                  // build: recurrence consts
    __shared__ float  s_smp[IVB][NNODE];          // build: samples
    __shared__ __align__(16) float4 sm[M_IV];     // eval: 16 KB table copy

    const int tid = threadIdx.x;

    // ---------------- phase A: build (blocks that own chunks) ----------
    const int nb = (gridDim.x < NCHUNK) ? gridDim.x : NCHUNK;
    if ((int)blockIdx.x < nb) {
        // recurrence table: tab[k] = {a_k, -b_k, w_{k+1}, 0}; tab[0].z = w_1
        for (int k = tid; k < NDEG; k += TPB) {
            float a = 0.0f, b = 0.0f;
            if (k >= 1) {
                a = (2.0f * k + 1.0f) / (float)(k + 1);
                b = -(float)k / (float)(k + 1);
            }
            float w = SQ.v[k + 1] * __ldg(coef + k);   // w_{k+1}
            tab[k] = make_float4(a, b, w, 0.0f);
        }
        __syncthreads();

        const int iv   = tid >> 2;                // 0..31
        const int node = tid & 3;                 // 0..3
        const double Delta = PI_D / M_IV;

        for (int cb = blockIdx.x; cb < NCHUNK; cb += gridDim.x) {
            const int j = cb * IVB + iv;
            double th = (j + 0.5) * Delta + 0.5 * Delta * U4.u[node];
            float  x  = (float)cos(th);

            float pm1 = 1.0f, p = x;
            float acc = tab[0].z * x;             // w_1 * P_1
#pragma unroll 8
            for (int k = 1; k < NDEG; ++k) {
                float4 q  = tab[k];
                float  pn = fmaf(q.x * x, p, q.y * pm1);
                acc = fmaf(q.z, pn, acc);
                pm1 = p; p = pn;
            }
            s_smp[iv][node] = acc;
            __syncthreads();

            double a = 0.0;
#pragma unroll
            for (int i = 0; i < NNODE; ++i)
                a += W4.w[node][i] * (double)s_smp[iv][i];
            g_rec[j * 4 + node] = (float)a;
            __syncthreads();
        }
        __threadfence();
        if (tid == 0) atomicAdd((int*)&g_done, 1);
    }

    // ---------------- phase B: global wait ----------------
    if (tid == 0) {
        while (g_done < nb) __nanosleep(64);
    }
    __syncthreads();
    __threadfence();   // acquire: order table reads after the flag

    // ---------------- phase C: stage table to smem ----------------
    {
        const float4* src = reinterpret_cast<const float4*>(g_rec);
        for (int i = tid; i < M_IV; i += TPB) sm[i] = src[i];
    }
    __syncthreads();

    // ---------------- phase D: evaluate ----------------
    float ct = 1.0f;
    if (ctp) {
        int iv   = *ctp;
        float fv = __int_as_float(iv);
        ct = (iv > 0 && iv < (1 << 20)) ? (float)iv : fv;
    }
    const float sc2     = 2.0f / ct;
    const float THSCALE = (float)(M_IV / PI_D);

    const long long base = ((long long)blockIdx.x * TPB + tid) * EV_V;
    if (base < n) {
        float tv[EV_V];
        bool full = (base + EV_V <= n);
        if (full) {
            float4 ta = *reinterpret_cast<const float4*>(t + base);
            tv[0] = ta.x; tv[1] = ta.y; tv[2] = ta.z; tv[3] = ta.w;
        } else {
#pragma unroll
            for (int v = 0; v < EV_V; ++v) {
                long long idx = base + v;
                tv[v] = (idx < n) ? t[idx] : 0.0f;
            }
        }

        float res[EV_V];
#pragma unroll
        for (int v = 0; v < EV_V; ++v) {
            float x  = fmaf(tv[v], sc2, -1.0f);
            x = fminf(fmaxf(x, -1.0f), 1.0f);
            float th = acosf(x);
            float f  = th * THSCALE;
            int   j  = min((int)f, M_IV - 1);
            float u  = fmaf(2.0f, f - (float)j, -1.0f);

            float4 m = sm[j];                     // one LDS.128 gather
            res[v] = fmaf(fmaf(fmaf(m.w, u, m.z), u, m.y), u, m.x);
        }

        if (full) {
            *reinterpret_cast<float4*>(out + base) =
                make_float4(res[0], res[1], res[2], res[3]);
        } else {
#pragma unroll
            for (int v = 0; v < EV_V; ++v) {
                long long idx = base + v;
                if (idx < n) out[idx] = res[v];
            }
        }
    }

    // ---------------- phase E: last-block reset (replay determinism) ----
    __syncthreads();
    if (tid == 0) {
        int prev = atomicAdd(&g_exit, 1);
        if (prev == (int)gridDim.x - 1) {
            g_exit = 0;
            g_done = 0;
            __threadfence();
        }
    }
}

// ---------------- launch ----------------

extern "C" void kernel_launch(void* const* d_in, const int* in_sizes, int n_in,
                              void* d_out, int out_size)
{
    // Identify inputs by size: big -> t, 1 -> curr_t, remaining -> coef
    int ti = -1, ci = -1, si = -1;
    for (int i = 0; i < n_in; ++i) {
        if (in_sizes[i] == out_size && ti < 0)      ti = i;
        else if (in_sizes[i] == 1 && si < 0)        si = i;
        else if (ci < 0)                            ci = i;
    }
    if (ti < 0) ti = 0;
    if (ci < 0) ci = (n_in > 1 ? 1 : 0);

    const float* t    = (const float*)d_in[ti];
    const float* coef = (const float*)d_in[ci];
    const int*   ct   = (si >= 0) ? (const int*)d_in[si] : nullptr;

    int n = out_size;
    int epb    = TPB * EV_V;                      // 512 elems/block
    int blocks = (n + epb - 1) / epb;             // 1024 for n=524288
    hippo_fused<<<blocks, TPB>>>(t, coef, ct, (float*)d_out, n);
}

// round 15
// speedup vs baseline: 1.9446x; 1.0959x over previous
#include <cuda_runtime.h>
#include <utility>
#include <math.h>

// =====================================================================
// HiPPO-LegS reconstruction:  out = F(x),  x = 2*t/curr_t - 1.
// F(cos(theta)) is a degree-256 trig polynomial -> piecewise cubic on
// M=1024 uniform theta-intervals (validated R13/R14, rel_err 5.2e-5).
//
// R15 = R14 fused kernel minus ALL runtime double precision:
//  - node x-values (input-independent!) baked at compile time into a
//    16KB __device__ float table (was: runtime cos(double), ~6us of
//    FP64 serialization that 1024 blocks waited on)
//  - 4x4 Chebyshev->monomial fit in float
//  - t/curr_t loads hoisted before the global spin (DRAM overlap)
// Structure: blocks 0..31 build the 16KB coeff table, threadfence,
// counter; all 1024 co-resident blocks spin, stage table to smem,
// evaluate (acosf -> index -> one LDS.128 -> 3-FMA Horner); last block
// resets counters for graph-replay determinism.
// =====================================================================

#define NDEG  256
#define M_IV  1024
#define NNODE 4
#define IVB   32
#define NCHUNK (M_IV / IVB)
#define TPB   128
#define EV_V  4

static constexpr double PI_D = 3.14159265358979323846;

// ---------------- constexpr helpers ----------------

__host__ __device__ constexpr double csqrt(double v) {
    double g = v < 1.0 ? 1.0 : v;
    for (int i = 0; i < 100; ++i) g = 0.5 * (g + v / g);
    return g;
}

__host__ __device__ constexpr double ccos(double x) {
    while (x >  PI_D) x -= 2.0 * PI_D;
    while (x < -PI_D) x += 2.0 * PI_D;
    double x2 = x * x, term = 1.0, sum = 0.0;
    for (int m = 0; m < 18; ++m) {
        sum += term;
        term *= -x2 / ((2.0 * m + 1.0) * (2.0 * m + 2.0));
    }
    return sum;
}

// sqrt(2m+1) table
struct SQT { float v[NDEG + 2]; };
template <size_t... I>
constexpr SQT make_sq(std::index_sequence<I...>) {
    return SQT{{ ((float)csqrt(2.0 * (double)I + 1.0))... }};
}
__constant__ SQT SQ = make_sq(std::make_index_sequence<NDEG + 2>{});

// node x table: x[j*4+i] = cos((j+0.5)*D + 0.5*D*u_i), u_i = cos(pi(2i+1)/8)
__host__ __device__ constexpr float xnode_of(int gid) {
    int j = gid / NNODE, node = gid % NNODE;
    double Delta = PI_D / M_IV;
    double u  = ccos(PI_D * (2 * node + 1) / 8.0);
    double th = (j + 0.5) * Delta + 0.5 * Delta * u;
    return (float)ccos(th);
}
struct XT { float v[M_IV * NNODE]; };
template <size_t... I>
constexpr XT make_xn(std::index_sequence<I...>) {
    return XT{{ xnode_of((int)I)... }};
}
__device__ const XT g_xn = make_xn(std::make_index_sequence<M_IV * NNODE>{});

// W4[q][i]: samples at 4 Chebyshev nodes -> monomial coeffs (float)
struct W4T { float w[NNODE][NNODE]; };
__host__ __device__ constexpr W4T make_W4() {
    W4T r{};
    for (int i = 0; i < NNODE; ++i) {
        double c[4] = {0.0, 0.0, 0.0, 0.0};
        for (int p = 0; p < 4; ++p) {
            double kp = (p == 0) ? 0.25 : 0.5;
            c[p] = kp * ccos(p * PI_D * (2 * i + 1) / 8.0);
        }
        r.w[0][i] = (float)(c[0] - c[2]);
        r.w[1][i] = (float)(c[1] - 3.0 * c[3]);
        r.w[2][i] = (float)(2.0 * c[2]);
        r.w[3][i] = (float)(4.0 * c[3]);
    }
    return r;
}
__constant__ W4T W4 = make_W4();

// ---------------- device scratch (static: no allocation) ----------------

__device__ __align__(16) float g_rec[M_IV * 4];   // 16 KB coeff table
__device__ volatile int g_done;
__device__ int g_exit;

// ---------------- fused kernel ----------------

__global__ __launch_bounds__(TPB) void hippo_fused(
    const float* __restrict__ t, const float* __restrict__ coef,
    const int* __restrict__ ctp, float* __restrict__ out, int n)
{
    __shared__ float4 tab[NDEG];
    __shared__ float  s_smp[IVB][NNODE];
    __shared__ __align__(16) float4 sm[M_IV];     // 16 KB table copy

    const int tid = threadIdx.x;

    // ---- hoisted input loads (overlap DRAM latency with build/spin) ----
    const long long base = ((long long)blockIdx.x * TPB + tid) * EV_V;
    bool active = (base < n);
    bool full   = (base + EV_V <= n);
    float tv[EV_V] = {0.f, 0.f, 0.f, 0.f};
    if (active) {
        if (full) {
            float4 ta = *reinterpret_cast<const float4*>(t + base);
            tv[0] = ta.x; tv[1] = ta.y; tv[2] = ta.z; tv[3] = ta.w;
        } else {
#pragma unroll
            for (int v = 0; v < EV_V; ++v) {
                long long idx = base + v;
                tv[v] = (idx < n) ? t[idx] : 0.0f;
            }
        }
    }
    float ct = 1.0f;
    if (ctp) {
        int iv   = *ctp;
        float fv = __int_as_float(iv);
        ct = (iv > 0 && iv < (1 << 20)) ? (float)iv : fv;
    }

    // ---------------- phase A: build (first NCHUNK blocks) --------------
    const int nb = (gridDim.x < NCHUNK) ? (int)gridDim.x : NCHUNK;
    if ((int)blockIdx.x < nb) {
        for (int k = tid; k < NDEG; k += TPB) {
            float a = 0.0f, b = 0.0f;
            if (k >= 1) {
                a = (2.0f * k + 1.0f) / (float)(k + 1);
                b = -(float)k / (float)(k + 1);
            }
            float w = SQ.v[k + 1] * __ldg(coef + k);   // w_{k+1}
            tab[k] = make_float4(a, b, w, 0.0f);
        }
        __syncthreads();

        const int iv   = tid >> 2;
        const int node = tid & 3;

        for (int cb = blockIdx.x; cb < NCHUNK; cb += gridDim.x) {
            const int j = cb * IVB + iv;
            float x = __ldg(&g_xn.v[j * NNODE + node]);  // compile-time node

            float pm1 = 1.0f, p = x;
            float acc = tab[0].z * x;                 // w_1 * P_1
#pragma unroll 8
            for (int k = 1; k < NDEG; ++k) {
                float4 q  = tab[k];
                float  pn = fmaf(q.x * x, p, q.y * pm1);
                acc = fmaf(q.z, pn, acc);
                pm1 = p; p = pn;
            }
            s_smp[iv][node] = acc;
            __syncthreads();

            float a = 0.0f;                           // float fit (no FP64)
#pragma unroll
            for (int i = 0; i < NNODE; ++i)
                a = fmaf(W4.w[node][i], s_smp[iv][i], a);
            g_rec[j * 4 + node] = a;
            __syncthreads();
        }
        __threadfence();
        if (tid == 0) atomicAdd((int*)&g_done, 1);
    }

    // ---------------- phase B: global wait ----------------
    if (tid == 0) {
        while (g_done < nb) __nanosleep(64);
    }
    __syncthreads();
    __threadfence();   // acquire

    // ---------------- phase C: stage table to smem ----------------
    {
        const float4* src = reinterpret_cast<const float4*>(g_rec);
        for (int i = tid; i < M_IV; i += TPB) sm[i] = src[i];
    }
    __syncthreads();

    // ---------------- phase D: evaluate ----------------
    const float sc2     = 2.0f / ct;
    const float THSCALE = (float)(M_IV / PI_D);

    if (active) {
        float res[EV_V];
#pragma unroll
        for (int v = 0; v < EV_V; ++v) {
            float x  = fmaf(tv[v], sc2, -1.0f);
            x = fminf(fmaxf(x, -1.0f), 1.0f);
            float th = acosf(x);
            float f  = th * THSCALE;
            int   j  = min((int)f, M_IV - 1);
            float u  = fmaf(2.0f, f - (float)j, -1.0f);

            float4 m = sm[j];                     // one LDS.128 gather
            res[v] = fmaf(fmaf(fmaf(m.w, u, m.z), u, m.y), u, m.x);
        }

        if (full) {
            *reinterpret_cast<float4*>(out + base) =
                make_float4(res[0], res[1], res[2], res[3]);
        } else {
#pragma unroll
            for (int v = 0; v < EV_V; ++v) {
                long long idx = base + v;
                if (idx < n) out[idx] = res[v];
            }
        }
    }

    // ---------------- phase E: last-block reset (replay determinism) ----
    __syncthreads();
    if (tid == 0) {
        int prev = atomicAdd(&g_exit, 1);
        if (prev == (int)gridDim.x - 1) {
            g_exit = 0;
            g_done = 0;
            __threadfence();
        }
    }
}

// ---------------- launch ----------------

extern "C" void kernel_launch(void* const* d_in, const int* in_sizes, int n_in,
                              void* d_out, int out_size)
{
    // Identify inputs by size: big -> t, 1 -> curr_t, remaining -> coef
    int ti = -1, ci = -1, si = -1;
    for (int i = 0; i < n_in; ++i) {
        if (in_sizes[i] == out_size && ti < 0)      ti = i;
        else if (in_sizes[i] == 1 && si < 0)        si = i;
        else if (ci < 0)                            ci = i;
    }
    if (ti < 0) ti = 0;
    if (ci < 0) ci = (n_in > 1 ? 1 : 0);

    const float* t    = (const float*)d_in[ti];
    const float* coef = (const float*)d_in[ci];
    const int*   ct   = (si >= 0) ? (const int*)d_in[si] : nullptr;

    int n = out_size;
    int epb    = TPB * EV_V;                      // 512 elems/block
    int blocks = (n + epb - 1) / epb;             // 1024 for n=524288
    hippo_fused<<<blocks, TPB>>>(t, coef, ct, (float*)d_out, n);
}

// round 16
// speedup vs baseline: 1.9698x; 1.0130x over previous
#include <cuda_runtime.h>
#include <utility>
#include <math.h>

// =====================================================================
// HiPPO-LegS reconstruction:  out = F(x),  x = 2*t/curr_t - 1.
// F(cos(theta)) is a degree-256 trig polynomial. R16 indexes the
// piecewise-cubic table by w = sqrt(1-|x|) with a sign split:
//   x>=0: theta = acos(1-w^2), dtheta/dw = 2/sqrt(2-w^2) in [1.41,2]
//   x<0 : w = sqrt(1+x), mirrored half
// -> uniform-w intervals give uniform phase coverage WITHOUT acosf:
// the index costs ONE sqrtf (acosf paid that internally plus ~12 more
// instrs + a long chain). M=2048 intervals (1024/half, 32KB table),
// half-interval phase <= 0.25 rad -> cubic fit error ~1e-5.
//
// Fused single kernel (R14/R15 structure): 32 builder blocks sample F
// at 4 Chebyshev nodes/interval (forward Legendre recurrence, float
// only, compile-time node-x table) + 4x4 constexpr fit -> 32KB global
// table; all 512 co-resident blocks spin on a counter, stage table to
// smem, evaluate; last block resets counters for replay determinism.
// Grid 512x256 (38KB smem -> 6 blocks/SM -> single wave guaranteed).
// =====================================================================

#define NDEG  256
#define MHALF 1024               // intervals per half
#define M_IV  (2 * MHALF)        // 2048 total
#define NNODE 4
#define IVB   64                 // intervals per builder chunk (TPB/4)
#define NCHUNK (M_IV / IVB)      // 32 chunks
#define TPB   256
#define EV_V  4

static constexpr double PI_D = 3.14159265358979323846;

// ---------------- constexpr helpers ----------------

__host__ __device__ constexpr double csqrt(double v) {
    double g = v < 1.0 ? 1.0 : v;
    for (int i = 0; i < 100; ++i) g = 0.5 * (g + v / g);
    return g;
}

__host__ __device__ constexpr double ccos(double x) {
    while (x >  PI_D) x -= 2.0 * PI_D;
    while (x < -PI_D) x += 2.0 * PI_D;
    double x2 = x * x, term = 1.0, sum = 0.0;
    for (int m = 0; m < 18; ++m) {
        sum += term;
        term *= -x2 / ((2.0 * m + 1.0) * (2.0 * m + 2.0));
    }
    return sum;
}

// sqrt(2m+1) table
struct SQT { float v[NDEG + 2]; };
template <size_t... I>
constexpr SQT make_sq(std::index_sequence<I...>) {
    return SQT{{ ((float)csqrt(2.0 * (double)I + 1.0))... }};
}
__constant__ SQT SQ = make_sq(std::make_index_sequence<NDEG + 2>{});

// node x table: interval J = h*MHALF + jj (h=0: x>=0, h=1: x<0),
// node i: w = (jj + 0.5 + 0.5*u_i)/MHALF, u_i = cos(pi(2i+1)/8),
// x = (h==0) ? 1 - w^2 : w^2 - 1.
__host__ __device__ constexpr float xnode_of(int gid) {
    int J = gid / NNODE, node = gid % NNODE;
    int h = J / MHALF, jj = J % MHALF;
    double u = ccos(PI_D * (2 * node + 1) / 8.0);
    double w = (jj + 0.5 + 0.5 * u) / (double)MHALF;
    double x = (h == 0) ? (1.0 - w * w) : (w * w - 1.0);
    return (float)x;
}
struct XT { float v[M_IV * NNODE]; };
template <size_t... I>
constexpr XT make_xn(std::index_sequence<I...>) {
    return XT{{ xnode_of((int)I)... }};
}
__device__ const XT g_xn = make_xn(std::make_index_sequence<M_IV * NNODE>{});

// W4[q][i]: samples at 4 Chebyshev nodes -> monomial coeffs (float)
struct W4T { float w[NNODE][NNODE]; };
__host__ __device__ constexpr W4T make_W4() {
    W4T r{};
    for (int i = 0; i < NNODE; ++i) {
        double c[4] = {0.0, 0.0, 0.0, 0.0};
        for (int p = 0; p < 4; ++p) {
            double kp = (p == 0) ? 0.25 : 0.5;
            c[p] = kp * ccos(p * PI_D * (2 * i + 1) / 8.0);
        }
        r.w[0][i] = (float)(c[0] - c[2]);
        r.w[1][i] = (float)(c[1] - 3.0 * c[3]);
        r.w[2][i] = (float)(2.0 * c[2]);
        r.w[3][i] = (float)(4.0 * c[3]);
    }
    return r;
}
__constant__ W4T W4 = make_W4();

// ---------------- device scratch (static: no allocation) ----------------

__device__ __align__(16) float g_rec[M_IV * 4];   // 32 KB coeff table
__device__ volatile int g_done;
__device__ int g_exit;

// ---------------- fused kernel ----------------

__global__ __launch_bounds__(TPB) void hippo_fused(
    const float* __restrict__ t, const float* __restrict__ coef,
    const int* __restrict__ ctp, float* __restrict__ out, int n)
{
    __shared__ float4 tab[NDEG];                  // 4 KB (build)
    __shared__ float  s_smp[IVB][NNODE];          // 1 KB (build)
    __shared__ __align__(16) float4 sm[M_IV];     // 32 KB table copy

    const int tid = threadIdx.x;

    // ---- hoisted input loads (overlap DRAM latency with build/spin) ----
    const long long base = ((long long)blockIdx.x * TPB + tid) * EV_V;
    bool active = (base < n);
    bool full   = (base + EV_V <= n);
    float tv[EV_V] = {0.f, 0.f, 0.f, 0.f};
    if (active) {
        if (full) {
            float4 ta = *reinterpret_cast<const float4*>(t + base);
            tv[0] = ta.x; tv[1] = ta.y; tv[2] = ta.z; tv[3] = ta.w;
        } else {
#pragma unroll
            for (int v = 0; v < EV_V; ++v) {
                long long idx = base + v;
                tv[v] = (idx < n) ? t[idx] : 0.0f;
            }
        }
    }
    float ct = 1.0f;
    if (ctp) {
        int iv   = *ctp;
        float fv = __int_as_float(iv);
        ct = (iv > 0 && iv < (1 << 20)) ? (float)iv : fv;
    }

    // ---------------- phase A: build (first NCHUNK blocks) --------------
    const int nb = (gridDim.x < NCHUNK) ? (int)gridDim.x : NCHUNK;
    if ((int)blockIdx.x < nb) {
        for (int k = tid; k < NDEG; k += TPB) {
            float a = 0.0f, b = 0.0f;
            if (k >= 1) {
                a = (2.0f * k + 1.0f) / (float)(k + 1);
                b = -(float)k / (float)(k + 1);
            }
            float w = SQ.v[k + 1] * __ldg(coef + k);   // w_{k+1}
            tab[k] = make_float4(a, b, w, 0.0f);
        }
        __syncthreads();

        const int iv   = tid >> 2;                // 0..63
        const int node = tid & 3;

        for (int cb = blockIdx.x; cb < NCHUNK; cb += gridDim.x) {
            const int J = cb * IVB + iv;
            float x = __ldg(&g_xn.v[J * NNODE + node]);

            float pm1 = 1.0f, p = x;
            float acc = tab[0].z * x;             // w_1 * P_1
#pragma unroll 8
            for (int k = 1; k < NDEG; ++k) {
                float4 q  = tab[k];
                float  pn = fmaf(q.x * x, p, q.y * pm1);
                acc = fmaf(q.z, pn, acc);
                pm1 = p; p = pn;
            }
            s_smp[iv][node] = acc;
            __syncthreads();

            float a = 0.0f;
#pragma unroll
            for (int i = 0; i < NNODE; ++i)
                a = fmaf(W4.w[node][i], s_smp[iv][i], a);
            g_rec[J * 4 + node] = a;
            __syncthreads();
        }
        __threadfence();
        if (tid == 0) atomicAdd((int*)&g_done, 1);
    }

    // ---------------- phase B: global wait ----------------
    if (tid == 0) {
        while (g_done < nb) __nanosleep(64);
    }
    __syncthreads();
    __threadfence();   // acquire

    // ---------------- phase C: stage table to smem ----------------
    {
        const float4* src = reinterpret_cast<const float4*>(g_rec);
        for (int i = tid; i < M_IV; i += TPB) sm[i] = src[i];
    }
    __syncthreads();

    // ---------------- phase D: evaluate ----------------
    const float sc2 = 2.0f / ct;

    if (active) {
        float res[EV_V];
#pragma unroll
        for (int v = 0; v < EV_V; ++v) {
            float x  = fmaf(tv[v], sc2, -1.0f);
            float ax = fminf(fabsf(x), 1.0f);
            float y  = 1.0f - ax;                 // exact for ax >= 0.5
            float w  = sqrtf(y);                  // one MUFU (no acosf!)
            int   j  = (int)(w * (float)MHALF);
            j = min(j, MHALF - 1);
            float u  = fmaf(w, 2.0f * (float)MHALF,
                            -(float)(2 * j + 1)); // single rounding
            int idx = j + ((x < 0.0f) ? MHALF : 0);

            float4 m = sm[idx];                   // one LDS.128 gather
            res[v] = fmaf(fmaf(fmaf(m.w, u, m.z), u, m.y), u, m.x);
        }

        if (full) {
            *reinterpret_cast<float4*>(out + base) =
                make_float4(res[0], res[1], res[2], res[3]);
        } else {
#pragma unroll
            for (int v = 0; v < EV_V; ++v) {
                long long idx = base + v;
                if (idx < n) out[idx] = res[v];
            }
        }
    }

    // ---------------- phase E: last-block reset (replay determinism) ----
    __syncthreads();
    if (tid == 0) {
        int prev = atomicAdd(&g_exit, 1);
        if (prev == (int)gridDim.x - 1) {
            g_exit = 0;
            g_done = 0;
            __threadfence();
        }
    }
}

// ---------------- launch ----------------

extern "C" void kernel_launch(void* const* d_in, const int* in_sizes, int n_in,
                              void* d_out, int out_size)
{
    // Identify inputs by size: big -> t, 1 -> curr_t, remaining -> coef
    int ti = -1, ci = -1, si = -1;
    for (int i = 0; i < n_in; ++i) {
        if (in_sizes[i] == out_size && ti < 0)      ti = i;
        else if (in_sizes[i] == 1 && si < 0)        si = i;
        else if (ci < 0)                            ci = i;
    }
    if (ti < 0) ti = 0;
    if (ci < 0) ci = (n_in > 1 ? 1 : 0);

    const float* t    = (const float*)d_in[ti];
    const float* coef = (const float*)d_in[ci];
    const int*   ct   = (si >= 0) ? (const int*)d_in[si] : nullptr;

    int n = out_size;
    int epb    = TPB * EV_V;                      // 1024 elems/block
    int blocks = (n + epb - 1) / epb;             // 512 for n=524288
    hippo_fused<<<blocks, TPB>>>(t, coef, ct, (float*)d_out, n);
}